// round 16
// baseline (speedup 1.0000x reference)
#include <cuda_runtime.h>

#define N_USERS 200000
#define N_ITEMS 100000
#define N_NODES 300000
#define N_EDGES 1500000
#define DIM 64
#define BERT 384

#define SCAN_B 1024
#define NB ((N_NODES + SCAN_B - 1) / SCAN_B)   // 293

// Scratch (static device globals — no allocs).
__device__ float g_buf[2][(size_t)N_NODES * DIM];      // fp32 x1, x2
__device__ int   g_cnt[N_NODES];                        // degree counts -> cursors
__device__ int   g_rowptr[N_NODES + 1];
__device__ int   g_blocksum[NB];
__device__ int   g_blockoff[NB];
__device__ __align__(16) int2 g_edge[N_EDGES];          // {col, val bits}
__device__ __align__(16) unsigned g_wfrag[24 * 1024];   // W tf32, fragment order

// ---------------------------------------------------------------------------
// CSR build: zero counts -> histogram -> 2-level warp-shuffle scan -> scatter
// ---------------------------------------------------------------------------
__global__ void zero_cnt_k()
{
    int i = blockIdx.x * blockDim.x + threadIdx.x;
    if (i < N_NODES) g_cnt[i] = 0;
}

__global__ void hist_k(const int* __restrict__ rows)
{
    int e = blockIdx.x * blockDim.x + threadIdx.x;
    if (e < N_EDGES) atomicAdd(&g_cnt[rows[e]], 1);
}

__global__ __launch_bounds__(SCAN_B) void scan1_k()
{
    __shared__ int wsum[32];
    int tid = threadIdx.x, lane = tid & 31, wid = tid >> 5;
    int i = blockIdx.x * SCAN_B + tid;
    int v = (i < N_NODES) ? g_cnt[i] : 0;
    int orig = v;
#pragma unroll
    for (int d = 1; d < 32; d <<= 1) {
        int t = __shfl_up_sync(0xFFFFFFFFu, v, d);
        if (lane >= d) v += t;
    }
    if (lane == 31) wsum[wid] = v;
    __syncthreads();
    if (wid == 0) {
        int w = wsum[lane];
#pragma unroll
        for (int d = 1; d < 32; d <<= 1) {
            int t = __shfl_up_sync(0xFFFFFFFFu, w, d);
            if (lane >= d) w += t;
        }
        wsum[lane] = w;
    }
    __syncthreads();
    int woff = wid ? wsum[wid - 1] : 0;
    int incl = v + woff;
    if (i < N_NODES) g_rowptr[i] = incl - orig;                  // exclusive in-block
    if (tid == SCAN_B - 1) g_blocksum[blockIdx.x] = incl;
}

__global__ __launch_bounds__(512) void scan2_k()
{
    __shared__ int wsum[16];
    int tid = threadIdx.x, lane = tid & 31, wid = tid >> 5;
    int v = (tid < NB) ? g_blocksum[tid] : 0;
    int orig = v;
#pragma unroll
    for (int d = 1; d < 32; d <<= 1) {
        int t = __shfl_up_sync(0xFFFFFFFFu, v, d);
        if (lane >= d) v += t;
    }
    if (lane == 31) wsum[wid] = v;
    __syncthreads();
    if (wid == 0) {
        int w = (lane < 16) ? wsum[lane] : 0;
#pragma unroll
        for (int d = 1; d < 16; d <<= 1) {
            int t = __shfl_up_sync(0xFFFFFFFFu, w, d);
            if (lane >= d) w += t;
        }
        if (lane < 16) wsum[lane] = w;
    }
    __syncthreads();
    int woff = wid ? wsum[wid - 1] : 0;
    if (tid < NB) g_blockoff[tid] = v + woff - orig;             // exclusive
    if (tid == 0) g_rowptr[N_NODES] = N_EDGES;
}

__global__ void scan3_k()
{
    int i = blockIdx.x * blockDim.x + threadIdx.x;
    if (i < N_NODES) {
        int r = g_rowptr[i] + g_blockoff[i >> 10];
        g_rowptr[i] = r;
        g_cnt[i] = r;                                            // cursor for scatter
    }
}

__global__ void scatter_k(const int* __restrict__ rows,
                          const int* __restrict__ cols,
                          const float* __restrict__ vals)
{
    int e = blockIdx.x * blockDim.x + threadIdx.x;
    if (e >= N_EDGES) return;
    int r = rows[e];
    int p = atomicAdd(&g_cnt[r], 1);
    g_edge[p] = make_int2(cols[e], __float_as_int(vals[e]));
}

// ---------------------------------------------------------------------------
// User init: out[u] = user_emb[u] + gender_emb[g] + age_emb[a]   (fp32 only)
// ---------------------------------------------------------------------------
__global__ void init_users_k(const float4* __restrict__ ue,
                             const float4* __restrict__ ge,
                             const float4* __restrict__ ae,
                             const int* __restrict__ ug,
                             const int* __restrict__ ua,
                             float4* __restrict__ out)
{
    int idx = blockIdx.x * blockDim.x + threadIdx.x;
    if (idx >= N_USERS * 16) return;
    int u = idx >> 4, s = idx & 15;
    int g = ug[u];
    int a = ua[u];
    float4 r = ue[idx];
    float4 gv = ge[g * 16 + s];
    float4 av = ae[a * 16 + s];
    r.x += gv.x + av.x; r.y += gv.y + av.y;
    r.z += gv.z + av.z; r.w += gv.w + av.w;
    out[idx] = r;
}

// ---------------------------------------------------------------------------
// TF32 GEMM with fragment-ordered smem (R10, measured 65.5us).
// ---------------------------------------------------------------------------
#define CVT_TF32(d, s) asm("cvt.rna.tf32.f32 %0, %1;" : "=r"(d) : "f"(s))

#define MMA_TF32(c, a0, a1, a2, a3, b0, b1)                                  \
    asm("mma.sync.aligned.m16n8k8.row.col.f32.tf32.tf32.f32 "               \
        "{%0,%1,%2,%3}, {%4,%5,%6,%7}, {%8,%9}, {%0,%1,%2,%3};"             \
        : "+f"((c)[0]), "+f"((c)[1]), "+f"((c)[2]), "+f"((c)[3])            \
        : "r"(a0), "r"(a1), "r"(a2), "r"(a3), "r"(b0), "r"(b1))

__global__ void wfrag_k(const float* __restrict__ W)
{
    int w = blockIdx.x * 256 + threadIdx.x;
    if (w >= 24 * 1024) return;
    int kt = w >> 10, r = w & 1023;
    int ipair = r >> 7;              // kk*4 + ntp
    int kk = ipair >> 2, ntp = ipair & 3;
    int r2 = r & 127;
    int lane = r2 >> 2, low = r2 & 3;
    int nthalf = low >> 1, reg = low & 1;
    int nt = ntp * 2 + nthalf;
    int gid = lane >> 2, tig = lane & 3;
    int n = nt * 8 + gid;
    int k = kt * 16 + kk * 8 + tig + reg * 4;
    unsigned u;
    CVT_TF32(u, W[(size_t)n * BERT + k]);
    g_wfrag[w] = u;
}

#define NKT (BERT / 16)     // 24
#define APAD 20

__global__ __launch_bounds__(128) void item_gemm_k(
    const float* __restrict__ bert,      // [N_ITEMS, 384]
    const float* __restrict__ ie,        // item_emb [N_ITEMS, 64]
    const float* __restrict__ ce,        // cat_emb [11, 64]
    const int* __restrict__ cat,
    float* __restrict__ out)
{
    __shared__ __align__(16) unsigned As[2][64 * APAD];   // [buf][m*20 + k]
    __shared__ __align__(16) uint4    Bs[2][256];          // [buf] fragment order

    int t    = threadIdx.x;
    int wid  = t >> 5;
    int lane = t & 31;
    int gid  = lane >> 2;        // 0..7
    int tig  = lane & 3;         // 0..3
    int wrow = wid * 16;
    int rb   = blockIdx.x * 64;

    float c[8][4];
#pragma unroll
    for (int nt = 0; nt < 8; nt++)
#pragma unroll
        for (int j = 0; j < 4; j++) c[nt][j] = 0.f;

    const uint4* wsrc = reinterpret_cast<const uint4*>(g_wfrag);
    float4 va[2];
    uint4  vb[2];

#define LOAD_AB(k0, kt)                                                      \
    {                                                                        \
        _Pragma("unroll")                                                    \
        for (int i = 0; i < 2; i++) {                                        \
            int q = i * 128 + t;                                             \
            int m = q >> 2, kq = q & 3;                                      \
            va[i] = (rb + m < N_ITEMS)                                       \
                ? *reinterpret_cast<const float4*>(                          \
                      bert + (size_t)(rb + m) * BERT + (k0) + kq * 4)        \
                : make_float4(0.f, 0.f, 0.f, 0.f);                           \
            vb[i] = __ldg(wsrc + (kt) * 256 + i * 128 + t);                  \
        }                                                                    \
    }
#define STORE_AB(buf)                                                        \
    {                                                                        \
        _Pragma("unroll")                                                    \
        for (int i = 0; i < 2; i++) {                                        \
            int q = i * 128 + t;                                             \
            int m = q >> 2, kq = q & 3;                                      \
            unsigned u0, u1, u2, u3;                                         \
            CVT_TF32(u0, va[i].x); CVT_TF32(u1, va[i].y);                    \
            CVT_TF32(u2, va[i].z); CVT_TF32(u3, va[i].w);                    \
            *reinterpret_cast<uint4*>(&As[buf][m * APAD + kq * 4]) =         \
                make_uint4(u0, u1, u2, u3);                                  \
            Bs[buf][i * 128 + t] = vb[i];                                    \
        }                                                                    \
    }

    LOAD_AB(0, 0);
    STORE_AB(0);
    __syncthreads();

#pragma unroll 1
    for (int kt = 0; kt < NKT; kt++) {
        int buf = kt & 1;
        if (kt + 1 < NKT) LOAD_AB((kt + 1) * 16, kt + 1);

#pragma unroll
        for (int kk = 0; kk < 2; kk++) {
            int kb = kk * 8;
            unsigned a0 = As[buf][(wrow + gid)     * APAD + kb + tig];
            unsigned a1 = As[buf][(wrow + gid + 8) * APAD + kb + tig];
            unsigned a2 = As[buf][(wrow + gid)     * APAD + kb + tig + 4];
            unsigned a3 = As[buf][(wrow + gid + 8) * APAD + kb + tig + 4];
#pragma unroll
            for (int ntp = 0; ntp < 4; ntp++) {
                uint4 bb = Bs[buf][(kk * 4 + ntp) * 32 + lane];
                MMA_TF32(c[2 * ntp],     a0, a1, a2, a3, bb.x, bb.y);
                MMA_TF32(c[2 * ntp + 1], a0, a1, a2, a3, bb.z, bb.w);
            }
        }

        if (kt + 1 < NKT) STORE_AB(buf ^ 1);
        __syncthreads();
    }

    // Epilogue: + item_emb + cat_emb (fp32 only).
    int r0 = rb + wrow + gid;
    int r1 = r0 + 8;
    int cc0 = (r0 < N_ITEMS) ? cat[r0] : 0;
    int cc1 = (r1 < N_ITEMS) ? cat[r1] : 0;
#pragma unroll
    for (int nt = 0; nt < 8; nt++) {
        int n0 = nt * 8 + tig * 2;
        if (r0 < N_ITEMS) {
            float2 e = *reinterpret_cast<const float2*>(ie + (size_t)r0 * 64 + n0);
            float2 v = *reinterpret_cast<const float2*>(ce + (size_t)cc0 * 64 + n0);
            float2 o = make_float2(c[nt][0] + e.x + v.x, c[nt][1] + e.y + v.y);
            *reinterpret_cast<float2*>(out + (size_t)(N_USERS + r0) * 64 + n0) = o;
        }
        if (r1 < N_ITEMS) {
            float2 e = *reinterpret_cast<const float2*>(ie + (size_t)r1 * 64 + n0);
            float2 v = *reinterpret_cast<const float2*>(ce + (size_t)cc1 * 64 + n0);
            float2 o = make_float2(c[nt][2] + e.x + v.x, c[nt][3] + e.y + v.y);
            *reinterpret_cast<float2*>(out + (size_t)(N_USERS + r1) * 64 + n0) = o;
        }
    }
}

// ---------------------------------------------------------------------------
// CSR gather SpMM, fp32 (no conversions — kills the F2F pipe bottleneck):
// 8 lanes per row, lane owns 2 float4 segments -> 2 independent LDG.128 per
// edge; 4/2/1 unroll ladder keeps up to 8 x-loads in flight.
// ---------------------------------------------------------------------------
struct f4x2 { float4 a, b; };

__device__ __forceinline__ f4x2 spmm_row8(const float4* __restrict__ x,
                                          int r, int s)
{
    int beg = __ldg(&g_rowptr[r]);
    int end = __ldg(&g_rowptr[r + 1]);
    float4 acc0 = make_float4(0.f, 0.f, 0.f, 0.f);
    float4 acc1 = make_float4(0.f, 0.f, 0.f, 0.f);
    int jj = beg;
    while (jj < end) {
        int n = end - jj;
        if (n >= 4) {
            int2 e0 = __ldg(&g_edge[jj + 0]);
            int2 e1 = __ldg(&g_edge[jj + 1]);
            int2 e2 = __ldg(&g_edge[jj + 2]);
            int2 e3 = __ldg(&g_edge[jj + 3]);
            float4 p0 = __ldg(&x[e0.x * 16 + 2 * s]);
            float4 q0 = __ldg(&x[e0.x * 16 + 2 * s + 1]);
            float4 p1 = __ldg(&x[e1.x * 16 + 2 * s]);
            float4 q1 = __ldg(&x[e1.x * 16 + 2 * s + 1]);
            float4 p2 = __ldg(&x[e2.x * 16 + 2 * s]);
            float4 q2 = __ldg(&x[e2.x * 16 + 2 * s + 1]);
            float4 p3 = __ldg(&x[e3.x * 16 + 2 * s]);
            float4 q3 = __ldg(&x[e3.x * 16 + 2 * s + 1]);
            float v0 = __int_as_float(e0.y);
            float v1 = __int_as_float(e1.y);
            float v2 = __int_as_float(e2.y);
            float v3 = __int_as_float(e3.y);
            acc0.x += v0 * p0.x; acc0.y += v0 * p0.y; acc0.z += v0 * p0.z; acc0.w += v0 * p0.w;
            acc1.x += v0 * q0.x; acc1.y += v0 * q0.y; acc1.z += v0 * q0.z; acc1.w += v0 * q0.w;
            acc0.x += v1 * p1.x; acc0.y += v1 * p1.y; acc0.z += v1 * p1.z; acc0.w += v1 * p1.w;
            acc1.x += v1 * q1.x; acc1.y += v1 * q1.y; acc1.z += v1 * q1.z; acc1.w += v1 * q1.w;
            acc0.x += v2 * p2.x; acc0.y += v2 * p2.y; acc0.z += v2 * p2.z; acc0.w += v2 * p2.w;
            acc1.x += v2 * q2.x; acc1.y += v2 * q2.y; acc1.z += v2 * q2.z; acc1.w += v2 * q2.w;
            acc0.x += v3 * p3.x; acc0.y += v3 * p3.y; acc0.z += v3 * p3.z; acc0.w += v3 * p3.w;
            acc1.x += v3 * q3.x; acc1.y += v3 * q3.y; acc1.z += v3 * q3.z; acc1.w += v3 * q3.w;
            jj += 4;
        } else if (n >= 2) {
            int2 e0 = __ldg(&g_edge[jj + 0]);
            int2 e1 = __ldg(&g_edge[jj + 1]);
            float4 p0 = __ldg(&x[e0.x * 16 + 2 * s]);
            float4 q0 = __ldg(&x[e0.x * 16 + 2 * s + 1]);
            float4 p1 = __ldg(&x[e1.x * 16 + 2 * s]);
            float4 q1 = __ldg(&x[e1.x * 16 + 2 * s + 1]);
            float v0 = __int_as_float(e0.y);
            float v1 = __int_as_float(e1.y);
            acc0.x += v0 * p0.x; acc0.y += v0 * p0.y; acc0.z += v0 * p0.z; acc0.w += v0 * p0.w;
            acc1.x += v0 * q0.x; acc1.y += v0 * q0.y; acc1.z += v0 * q0.z; acc1.w += v0 * q0.w;
            acc0.x += v1 * p1.x; acc0.y += v1 * p1.y; acc0.z += v1 * p1.z; acc0.w += v1 * p1.w;
            acc1.x += v1 * q1.x; acc1.y += v1 * q1.y; acc1.z += v1 * q1.z; acc1.w += v1 * q1.w;
            jj += 2;
        } else {
            int2 e0 = __ldg(&g_edge[jj]);
            float4 p0 = __ldg(&x[e0.x * 16 + 2 * s]);
            float4 q0 = __ldg(&x[e0.x * 16 + 2 * s + 1]);
            float v0 = __int_as_float(e0.y);
            acc0.x += v0 * p0.x; acc0.y += v0 * p0.y; acc0.z += v0 * p0.z; acc0.w += v0 * p0.w;
            acc1.x += v0 * q0.x; acc1.y += v0 * q0.y; acc1.z += v0 * q0.z; acc1.w += v0 * q0.w;
            jj += 1;
        }
    }
    f4x2 r2; r2.a = acc0; r2.b = acc1;
    return r2;
}

__global__ __launch_bounds__(256) void spmm_gather_k(const float4* __restrict__ x,
                                                     float4* __restrict__ y)
{
    int tid = blockIdx.x * blockDim.x + threadIdx.x;
    int r = tid >> 3;
    if (r >= N_NODES) return;
    int s = tid & 7;
    f4x2 acc = spmm_row8(x, r, s);
    y[r * 16 + 2 * s]     = acc.a;
    y[r * 16 + 2 * s + 1] = acc.b;
}

// Last layer fused with the mean: out = (x0 + x1 + x2 + A*x2) / 4
__global__ __launch_bounds__(256) void spmm_final_k(const float4* __restrict__ x,  // x2
                                                    const float4* __restrict__ b1, // x1
                                                    float4* __restrict__ out)      // x0 in, result out
{
    int tid = blockIdx.x * blockDim.x + threadIdx.x;
    int r = tid >> 3;
    if (r >= N_NODES) return;
    int s = tid & 7;
    f4x2 acc = spmm_row8(x, r, s);
#pragma unroll
    for (int h = 0; h < 2; h++) {
        int o = r * 16 + 2 * s + h;
        float4 ac = h ? acc.b : acc.a;
        float4 a0 = out[o];
        float4 a1 = b1[o];
        float4 a2 = x[o];
        float4 v;
        v.x = (a0.x + a1.x + a2.x + ac.x) * 0.25f;
        v.y = (a0.y + a1.y + a2.y + ac.y) * 0.25f;
        v.z = (a0.z + a1.z + a2.z + ac.z) * 0.25f;
        v.w = (a0.w + a1.w + a2.w + ac.w) * 0.25f;
        out[o] = v;
    }
}

// ---------------------------------------------------------------------------
extern "C" void kernel_launch(void* const* d_in, const int* in_sizes, int n_in,
                              void* d_out, int out_size)
{
    const float* user_emb    = (const float*)d_in[0];
    const float* item_emb    = (const float*)d_in[1];
    const float* gender_emb  = (const float*)d_in[2];
    const float* age_emb     = (const float*)d_in[3];
    const float* cat_emb     = (const float*)d_in[4];
    const float* bert_proj_w = (const float*)d_in[5];
    const float* item_bert   = (const float*)d_in[6];
    const float* adj_val     = (const float*)d_in[7];
    const int*   user_gender = (const int*)d_in[8];
    const int*   user_age    = (const int*)d_in[9];
    const int*   item_cat    = (const int*)d_in[10];
    const int*   adj_row     = (const int*)d_in[11];
    const int*   adj_col     = (const int*)d_in[12];
    float4* out = (float4*)d_out;

    (void)in_sizes; (void)n_in; (void)out_size;

    float4* buf0; cudaGetSymbolAddress((void**)&buf0, g_buf);      // x1
    float4* buf1 = buf0 + (size_t)N_NODES * 16;                    // x2

    const int eg = (N_EDGES + 255) / 256;
    const int ng = (N_NODES + 255) / 256;

    // item_gemm stays at launch index 3 (ncu profiles index 3).
    zero_cnt_k<<<ng, 256>>>();                                     // 0
    hist_k<<<eg, 256>>>(adj_row);                                  // 1
    wfrag_k<<<96, 256>>>(bert_proj_w);                             // 2
    item_gemm_k<<<(N_ITEMS + 63) / 64, 128>>>(                     // 3 <- profiled
        item_bert, item_emb, cat_emb, item_cat, (float*)d_out);
    scan1_k<<<NB, SCAN_B>>>();                                     // 4
    scan2_k<<<1, 512>>>();                                         // 5
    scan3_k<<<ng, 256>>>();                                        // 6
    scatter_k<<<eg, 256>>>(adj_row, adj_col, adj_val);             // 7
    init_users_k<<<(N_USERS * 16 + 255) / 256, 256>>>(             // 8
        (const float4*)user_emb, (const float4*)gender_emb,
        (const float4*)age_emb, user_gender, user_age, out);

    const int sg = (N_NODES * 8 + 255) / 256;
    spmm_gather_k<<<sg, 256>>>(out,  buf0);          // x1 = A x0
    spmm_gather_k<<<sg, 256>>>(buf0, buf1);          // x2 = A x1
    spmm_final_k<<<sg, 256>>>(buf1, buf0, out);      // out = (x0+x1+x2+A x2)/4
}

// round 17
// speedup vs baseline: 1.3194x; 1.3194x over previous
#include <cuda_runtime.h>
#include <cuda_fp16.h>

#define N_USERS 200000
#define N_ITEMS 100000
#define N_NODES 300000
#define N_EDGES 1500000
#define DIM 64
#define BERT 384

#define SCAN_B 1024
#define NB ((N_NODES + SCAN_B - 1) / SCAN_B)   // 293

// Scratch (static device globals — no allocs).
__device__ __align__(16) __half g_hx[2][(size_t)N_NODES * DIM];  // fp16 x buffers
__device__ int   g_cnt[N_NODES];                        // degree counts -> cursors
__device__ int   g_rowptr[N_NODES + 1];
__device__ int   g_blocksum[NB];
__device__ int   g_blockoff[NB];
__device__ __align__(16) int2 g_edge[N_EDGES];          // {col, val bits}
__device__ __align__(16) unsigned g_wfrag[24 * 1024];   // W fp16, fragment order (12288 used)

// ---------------------------------------------------------------------------
// prep_k: zero counts + W -> fp16 MMA-fragment-order conversion.
// Fragment word layout (m16n8k16, row.col):
//   word = kt*512 + q*128 + lane*4 + wp,  q = ntile pair, wp in 0..3:
//   nt = 2q + (wp>>1); khalf = wp&1; gid=lane>>2; tig=lane&3
//   content = half2( W[nt*8+gid][kt*16+khalf*8+tig*2],  same k+1 )
// ---------------------------------------------------------------------------
__global__ void prep_k(const float* __restrict__ W)
{
    int i = blockIdx.x * 256 + threadIdx.x;
    if (i < N_NODES) g_cnt[i] = 0;
    if (i < 24 * 512) {
        int kt = i >> 9, r = i & 511;
        int q = r >> 7, r2 = r & 127;
        int lane = r2 >> 2, wp = r2 & 3;
        int gid = lane >> 2, tig = lane & 3;
        int nt = 2 * q + (wp >> 1);
        int n = nt * 8 + gid;
        int kb = kt * 16 + (wp & 1) * 8 + tig * 2;
        __half2 h = __floats2half2_rn(W[(size_t)n * BERT + kb],
                                      W[(size_t)n * BERT + kb + 1]);
        g_wfrag[i] = *reinterpret_cast<unsigned*>(&h);
    }
}

// ---------------------------------------------------------------------------
// hist: degree histogram (REDG-throughput bound; unchanged)
// ---------------------------------------------------------------------------
__global__ void hist_k(const int* __restrict__ rows)
{
    int e = blockIdx.x * blockDim.x + threadIdx.x;
    if (e < N_EDGES) atomicAdd(&g_cnt[rows[e]], 1);
}

// ---------------------------------------------------------------------------
// warp-shuffle scans (R11, unchanged)
// ---------------------------------------------------------------------------
__global__ __launch_bounds__(SCAN_B) void scan1_k()
{
    __shared__ int wsum[32];
    int tid = threadIdx.x, lane = tid & 31, wid = tid >> 5;
    int i = blockIdx.x * SCAN_B + tid;
    int v = (i < N_NODES) ? g_cnt[i] : 0;
    int orig = v;
#pragma unroll
    for (int d = 1; d < 32; d <<= 1) {
        int t = __shfl_up_sync(0xFFFFFFFFu, v, d);
        if (lane >= d) v += t;
    }
    if (lane == 31) wsum[wid] = v;
    __syncthreads();
    if (wid == 0) {
        int w = wsum[lane];
#pragma unroll
        for (int d = 1; d < 32; d <<= 1) {
            int t = __shfl_up_sync(0xFFFFFFFFu, w, d);
            if (lane >= d) w += t;
        }
        wsum[lane] = w;
    }
    __syncthreads();
    int woff = wid ? wsum[wid - 1] : 0;
    int incl = v + woff;
    if (i < N_NODES) g_rowptr[i] = incl - orig;                  // exclusive in-block
    if (tid == SCAN_B - 1) g_blocksum[blockIdx.x] = incl;
}

__global__ __launch_bounds__(512) void scan2_k()
{
    __shared__ int wsum[16];
    int tid = threadIdx.x, lane = tid & 31, wid = tid >> 5;
    int v = (tid < NB) ? g_blocksum[tid] : 0;
    int orig = v;
#pragma unroll
    for (int d = 1; d < 32; d <<= 1) {
        int t = __shfl_up_sync(0xFFFFFFFFu, v, d);
        if (lane >= d) v += t;
    }
    if (lane == 31) wsum[wid] = v;
    __syncthreads();
    if (wid == 0) {
        int w = (lane < 16) ? wsum[lane] : 0;
#pragma unroll
        for (int d = 1; d < 16; d <<= 1) {
            int t = __shfl_up_sync(0xFFFFFFFFu, w, d);
            if (lane >= d) w += t;
        }
        if (lane < 16) wsum[lane] = w;
    }
    __syncthreads();
    int woff = wid ? wsum[wid - 1] : 0;
    if (tid < NB) g_blockoff[tid] = v + woff - orig;             // exclusive
    if (tid == 0) g_rowptr[N_NODES] = N_EDGES;
}

__global__ void scan3_k()
{
    int i = blockIdx.x * blockDim.x + threadIdx.x;
    if (i < N_NODES) {
        int r = g_rowptr[i] + g_blockoff[i >> 10];
        g_rowptr[i] = r;
        g_cnt[i] = r;                                            // cursor for scatter
    }
}

// ---------------------------------------------------------------------------
// scatter: 4 edges per thread -> 4 independent atomic->store chains (MLP x4)
// ---------------------------------------------------------------------------
__global__ void scatter_k(const int* __restrict__ rows,
                          const int* __restrict__ cols,
                          const float* __restrict__ vals)
{
    int b4 = (blockIdx.x * blockDim.x + threadIdx.x) * 4;
    if (b4 >= N_EDGES) return;
    int4   r4 = __ldg(reinterpret_cast<const int4*>(rows + b4));
    int4   c4 = __ldg(reinterpret_cast<const int4*>(cols + b4));
    float4 v4 = __ldg(reinterpret_cast<const float4*>(vals + b4));
    int p0 = atomicAdd(&g_cnt[r4.x], 1);
    int p1 = atomicAdd(&g_cnt[r4.y], 1);
    int p2 = atomicAdd(&g_cnt[r4.z], 1);
    int p3 = atomicAdd(&g_cnt[r4.w], 1);
    g_edge[p0] = make_int2(c4.x, __float_as_int(v4.x));
    g_edge[p1] = make_int2(c4.y, __float_as_int(v4.y));
    g_edge[p2] = make_int2(c4.z, __float_as_int(v4.z));
    g_edge[p3] = make_int2(c4.w, __float_as_int(v4.w));
}

// ---------------------------------------------------------------------------
// User init: fp32 to d_out, fp16 copy to g_hx[0]  (R11, unchanged)
// ---------------------------------------------------------------------------
__global__ void init_users_k(const float4* __restrict__ ue,
                             const float4* __restrict__ ge,
                             const float4* __restrict__ ae,
                             const int* __restrict__ ug,
                             const int* __restrict__ ua,
                             float4* __restrict__ out)
{
    int idx = blockIdx.x * blockDim.x + threadIdx.x;
    if (idx >= N_USERS * 16) return;
    int u = idx >> 4, s = idx & 15;
    int g = ug[u];
    int a = ua[u];
    float4 r = ue[idx];
    float4 gv = ge[g * 16 + s];
    float4 av = ae[a * 16 + s];
    r.x += gv.x + av.x; r.y += gv.y + av.y;
    r.z += gv.z + av.z; r.w += gv.w + av.w;
    out[idx] = r;
    __half2 h0 = __floats2half2_rn(r.x, r.y);
    __half2 h1 = __floats2half2_rn(r.z, r.w);
    uint2 p;
    p.x = *reinterpret_cast<unsigned*>(&h0);
    p.y = *reinterpret_cast<unsigned*>(&h1);
    reinterpret_cast<uint2*>(g_hx[0])[idx] = p;
}

// ---------------------------------------------------------------------------
// Item GEMM via fp16 MMA (m16n8k16, f32 accum).  Same 10-bit mantissa as
// tf32 -> identical precision; half the smem bytes and half the MMA steps.
// BM=64, 128 thr, warp w owns rows w*16..w*16+15, all 8 ntiles.
// A smem: [m][12 words] (8 half2 data + 4 pad -> conflict-free scalar LDS).
// B smem: fragment-ordered uint4 (copied from g_wfrag, 1 LDG.128/thread/tile).
// Double-buffered with register prefetch (R10 skeleton).
// ---------------------------------------------------------------------------
#define NKT (BERT / 16)     // 24
#define ASTR 12

#define MMA_F16(c, a0, a1, a2, a3, b0, b1)                                   \
    asm("mma.sync.aligned.m16n8k16.row.col.f32.f16.f16.f32 "                \
        "{%0,%1,%2,%3}, {%4,%5,%6,%7}, {%8,%9}, {%0,%1,%2,%3};"             \
        : "+f"((c)[0]), "+f"((c)[1]), "+f"((c)[2]), "+f"((c)[3])            \
        : "r"(a0), "r"(a1), "r"(a2), "r"(a3), "r"(b0), "r"(b1))

__device__ __forceinline__ unsigned pack_h2(float a, float b)
{
    __half2 h = __floats2half2_rn(a, b);
    return *reinterpret_cast<unsigned*>(&h);
}

__global__ __launch_bounds__(128) void item_gemm_k(
    const float* __restrict__ bert,      // [N_ITEMS, 384]
    const float* __restrict__ ie,        // item_emb [N_ITEMS, 64]
    const float* __restrict__ ce,        // cat_emb [11, 64]
    const int* __restrict__ cat,
    float* __restrict__ out)
{
    __shared__ __align__(16) unsigned As[2][64 * ASTR];   // [buf][m*12 + khalf2]
    __shared__ __align__(16) uint4    Bs[2][128];          // [buf] fragment order

    int t    = threadIdx.x;
    int wid  = t >> 5;
    int lane = t & 31;
    int gid  = lane >> 2;        // 0..7
    int tig  = lane & 3;         // 0..3
    int wrow = wid * 16;
    int rb   = blockIdx.x * 64;

    float c[8][4];
#pragma unroll
    for (int nt = 0; nt < 8; nt++)
#pragma unroll
        for (int j = 0; j < 4; j++) c[nt][j] = 0.f;

    const uint4* wsrc = reinterpret_cast<const uint4*>(g_wfrag);
    float4 va[2];
    uint4  vb;

#define LOAD_AB(k0, kt)                                                      \
    {                                                                        \
        _Pragma("unroll")                                                    \
        for (int i = 0; i < 2; i++) {                                        \
            int q = i * 128 + t;                                             \
            int m = q >> 2, kq = q & 3;                                      \
            va[i] = (rb + m < N_ITEMS)                                       \
                ? *reinterpret_cast<const float4*>(                          \
                      bert + (size_t)(rb + m) * BERT + (k0) + kq * 4)        \
                : make_float4(0.f, 0.f, 0.f, 0.f);                           \
        }                                                                    \
        vb = __ldg(wsrc + (kt) * 128 + t);                                   \
    }
#define STORE_AB(buf)                                                        \
    {                                                                        \
        _Pragma("unroll")                                                    \
        for (int i = 0; i < 2; i++) {                                        \
            int q = i * 128 + t;                                             \
            int m = q >> 2, kq = q & 3;                                      \
            uint2 hp;                                                        \
            hp.x = pack_h2(va[i].x, va[i].y);                                \
            hp.y = pack_h2(va[i].z, va[i].w);                                \
            *reinterpret_cast<uint2*>(&As[buf][m * ASTR + kq * 2]) = hp;     \
        }                                                                    \
        Bs[buf][t] = vb;                                                     \
    }

    LOAD_AB(0, 0);
    STORE_AB(0);
    __syncthreads();

#pragma unroll 1
    for (int kt = 0; kt < NKT; kt++) {
        int buf = kt & 1;
        if (kt + 1 < NKT) LOAD_AB((kt + 1) * 16, kt + 1);

        unsigned a0 = As[buf][(wrow + gid)     * ASTR + tig];
        unsigned a1 = As[buf][(wrow + gid + 8) * ASTR + tig];
        unsigned a2 = As[buf][(wrow + gid)     * ASTR + tig + 4];
        unsigned a3 = As[buf][(wrow + gid + 8) * ASTR + tig + 4];
#pragma unroll
        for (int q = 0; q < 4; q++) {
            uint4 bb = Bs[buf][q * 32 + lane];
            MMA_F16(c[2 * q],     a0, a1, a2, a3, bb.x, bb.y);
            MMA_F16(c[2 * q + 1], a0, a1, a2, a3, bb.z, bb.w);
        }

        if (kt + 1 < NKT) STORE_AB(buf ^ 1);
        __syncthreads();
    }

    // Epilogue: + item_emb + cat_emb; fp32 to out, fp16 copy to g_hx[0].
    int r0 = rb + wrow + gid;
    int r1 = r0 + 8;
    int cc0 = (r0 < N_ITEMS) ? cat[r0] : 0;
    int cc1 = (r1 < N_ITEMS) ? cat[r1] : 0;
    __half* hx0 = g_hx[0];
#pragma unroll
    for (int nt = 0; nt < 8; nt++) {
        int n0 = nt * 8 + tig * 2;
        if (r0 < N_ITEMS) {
            float2 e = *reinterpret_cast<const float2*>(ie + (size_t)r0 * 64 + n0);
            float2 v = *reinterpret_cast<const float2*>(ce + (size_t)cc0 * 64 + n0);
            float2 o = make_float2(c[nt][0] + e.x + v.x, c[nt][1] + e.y + v.y);
            *reinterpret_cast<float2*>(out + (size_t)(N_USERS + r0) * 64 + n0) = o;
            *reinterpret_cast<unsigned*>(hx0 + (size_t)(N_USERS + r0) * 64 + n0) =
                pack_h2(o.x, o.y);
        }
        if (r1 < N_ITEMS) {
            float2 e = *reinterpret_cast<const float2*>(ie + (size_t)r1 * 64 + n0);
            float2 v = *reinterpret_cast<const float2*>(ce + (size_t)cc1 * 64 + n0);
            float2 o = make_float2(c[nt][2] + e.x + v.x, c[nt][3] + e.y + v.y);
            *reinterpret_cast<float2*>(out + (size_t)(N_USERS + r1) * 64 + n0) = o;
            *reinterpret_cast<unsigned*>(hx0 + (size_t)(N_USERS + r1) * 64 + n0) =
                pack_h2(o.x, o.y);
        }
    }
}

// ---------------------------------------------------------------------------
// CSR gather SpMM on fp16 features (R11 best, unchanged): 8 lanes per row,
// lane owns 16B.  4/2/1 unroll ladder.  Compute fp32, store fp16.
// ---------------------------------------------------------------------------
__device__ __forceinline__ void acc_h(float* a, uint4 xv, float v)
{
    float2 f0 = __half22float2(*reinterpret_cast<__half2*>(&xv.x));
    float2 f1 = __half22float2(*reinterpret_cast<__half2*>(&xv.y));
    float2 f2 = __half22float2(*reinterpret_cast<__half2*>(&xv.z));
    float2 f3 = __half22float2(*reinterpret_cast<__half2*>(&xv.w));
    a[0] += v * f0.x; a[1] += v * f0.y;
    a[2] += v * f1.x; a[3] += v * f1.y;
    a[4] += v * f2.x; a[5] += v * f2.y;
    a[6] += v * f3.x; a[7] += v * f3.y;
}

__device__ __forceinline__ void spmm_row_h(const uint4* __restrict__ x,
                                           int r, int s, float* acc)
{
    int beg = __ldg(&g_rowptr[r]);
    int end = __ldg(&g_rowptr[r + 1]);
    int jj = beg;
    while (jj < end) {
        int n = end - jj;
        if (n >= 4) {
            int2 e0 = __ldg(&g_edge[jj + 0]);
            int2 e1 = __ldg(&g_edge[jj + 1]);
            int2 e2 = __ldg(&g_edge[jj + 2]);
            int2 e3 = __ldg(&g_edge[jj + 3]);
            uint4 x0 = __ldg(&x[e0.x * 8 + s]);
            uint4 x1 = __ldg(&x[e1.x * 8 + s]);
            uint4 x2 = __ldg(&x[e2.x * 8 + s]);
            uint4 x3 = __ldg(&x[e3.x * 8 + s]);
            acc_h(acc, x0, __int_as_float(e0.y));
            acc_h(acc, x1, __int_as_float(e1.y));
            acc_h(acc, x2, __int_as_float(e2.y));
            acc_h(acc, x3, __int_as_float(e3.y));
            jj += 4;
        } else if (n >= 2) {
            int2 e0 = __ldg(&g_edge[jj + 0]);
            int2 e1 = __ldg(&g_edge[jj + 1]);
            uint4 x0 = __ldg(&x[e0.x * 8 + s]);
            uint4 x1 = __ldg(&x[e1.x * 8 + s]);
            acc_h(acc, x0, __int_as_float(e0.y));
            acc_h(acc, x1, __int_as_float(e1.y));
            jj += 2;
        } else {
            int2 e0 = __ldg(&g_edge[jj]);
            uint4 x0 = __ldg(&x[e0.x * 8 + s]);
            acc_h(acc, x0, __int_as_float(e0.y));
            jj += 1;
        }
    }
}

__device__ __forceinline__ uint4 pack_h8(const float* a)
{
    __half2 h0 = __floats2half2_rn(a[0], a[1]);
    __half2 h1 = __floats2half2_rn(a[2], a[3]);
    __half2 h2 = __floats2half2_rn(a[4], a[5]);
    __half2 h3 = __floats2half2_rn(a[6], a[7]);
    uint4 o;
    o.x = *reinterpret_cast<unsigned*>(&h0);
    o.y = *reinterpret_cast<unsigned*>(&h1);
    o.z = *reinterpret_cast<unsigned*>(&h2);
    o.w = *reinterpret_cast<unsigned*>(&h3);
    return o;
}

__global__ __launch_bounds__(256) void spmm_gather_h(int xs)
{
    int tid = blockIdx.x * blockDim.x + threadIdx.x;
    int r = tid >> 3;
    if (r >= N_NODES) return;
    int s = tid & 7;
    const uint4* x = reinterpret_cast<const uint4*>(g_hx[xs]);
    uint4* y = reinterpret_cast<uint4*>(g_hx[xs ^ 1]);
    float acc[8] = {0.f, 0.f, 0.f, 0.f, 0.f, 0.f, 0.f, 0.f};
    spmm_row_h(x, r, s, acc);
    y[r * 8 + s] = pack_h8(acc);
}

// Final: out = (x0 + x1 + x2 + A*x2) / 4.  x1 = g_hx[1], x2 = g_hx[0].
__global__ __launch_bounds__(256) void spmm_final_k(float* __restrict__ out)
{
    int tid = blockIdx.x * blockDim.x + threadIdx.x;
    int r = tid >> 3;
    if (r >= N_NODES) return;
    int s = tid & 7;
    const uint4* x2 = reinterpret_cast<const uint4*>(g_hx[0]);
    const uint4* x1 = reinterpret_cast<const uint4*>(g_hx[1]);
    float acc[8] = {0.f, 0.f, 0.f, 0.f, 0.f, 0.f, 0.f, 0.f};
    spmm_row_h(x2, r, s, acc);                    // A * x2
    acc_h(acc, __ldg(&x1[r * 8 + s]), 1.f);       // + x1
    acc_h(acc, __ldg(&x2[r * 8 + s]), 1.f);       // + x2
    float4* op = reinterpret_cast<float4*>(out + (size_t)r * 64 + s * 8);
    float4 a0 = op[0];
    float4 a1 = op[1];
    a0.x = (a0.x + acc[0]) * 0.25f; a0.y = (a0.y + acc[1]) * 0.25f;
    a0.z = (a0.z + acc[2]) * 0.25f; a0.w = (a0.w + acc[3]) * 0.25f;
    a1.x = (a1.x + acc[4]) * 0.25f; a1.y = (a1.y + acc[5]) * 0.25f;
    a1.z = (a1.z + acc[6]) * 0.25f; a1.w = (a1.w + acc[7]) * 0.25f;
    op[0] = a0;
    op[1] = a1;
}

// ---------------------------------------------------------------------------
extern "C" void kernel_launch(void* const* d_in, const int* in_sizes, int n_in,
                              void* d_out, int out_size)
{
    const float* user_emb    = (const float*)d_in[0];
    const float* item_emb    = (const float*)d_in[1];
    const float* gender_emb  = (const float*)d_in[2];
    const float* age_emb     = (const float*)d_in[3];
    const float* cat_emb     = (const float*)d_in[4];
    const float* bert_proj_w = (const float*)d_in[5];
    const float* item_bert   = (const float*)d_in[6];
    const float* adj_val     = (const float*)d_in[7];
    const int*   user_gender = (const int*)d_in[8];
    const int*   user_age    = (const int*)d_in[9];
    const int*   item_cat    = (const int*)d_in[10];
    const int*   adj_row     = (const int*)d_in[11];
    const int*   adj_col     = (const int*)d_in[12];
    float4* out = (float4*)d_out;

    (void)in_sizes; (void)n_in; (void)out_size;

    const int eg = (N_EDGES + 255) / 256;
    const int ng = (N_NODES + 255) / 256;

    // item_gemm at launch index 3 (ncu profiles index 3).
    prep_k<<<ng, 256>>>(bert_proj_w);                              // 0
    hist_k<<<eg, 256>>>(adj_row);                                  // 1
    init_users_k<<<(N_USERS * 16 + 255) / 256, 256>>>(             // 2
        (const float4*)user_emb, (const float4*)gender_emb,
        (const float4*)age_emb, user_gender, user_age, out);
    item_gemm_k<<<(N_ITEMS + 63) / 64, 128>>>(                     // 3 <- profiled
        item_bert, item_emb, cat_emb, item_cat, (float*)d_out);
    scan1_k<<<NB, SCAN_B>>>();                                     // 4
    scan2_k<<<1, 512>>>();                                         // 5
    scan3_k<<<ng, 256>>>();                                        // 6
    scatter_k<<<(N_EDGES / 4 + 255) / 256, 256>>>(                 // 7
        adj_row, adj_col, adj_val);
    const int sg = (N_NODES * 8 + 255) / 256;
    spmm_gather_h<<<sg, 256>>>(0);                   // 8: x1 = A x0
    spmm_gather_h<<<sg, 256>>>(1);                   // 9: x2 = A x1
    spmm_final_k<<<sg, 256>>>((float*)d_out);        // 10: out = (x0+x1+x2+A x2)/4
}